// round 9
// baseline (speedup 1.0000x reference)
#include <cuda_runtime.h>
#include <cuda_bf16.h>
#include <math.h>

// EMDLoss: mean over (b,n) of min_m ||pred[b,n]-target[b,m]||, B=32, N=M=4096, d=3.
// Exact grid NN: targets raster-binned, preds Morton-binned (sorted for warp
// coherence). Pass 1: warp of 32 adjacent preds scans the bbox+1 neighborhood
// with broadcast loads; exact bbox-face stopping bound. Pass 2: failing preds
// brute-force over their batch's 4096 binned targets.

#define EMD_B 32
#define EMD_N 4096
#define EMD_M 4096

#define G      32
#define NCELLS (G * G * G)           // 32768 per batch
#define TCELLS (EMD_B * NCELLS)      // 1,048,576 (per side)
#define TOT2   (2 * TCELLS)
#define XMIN   (-4.0f)
#define H      0.25f
#define INVH   4.0f
#define VOLCAP 1024

#define NPTS   (EMD_B * EMD_M)       // 131072
#define INVTOT (1.0f / (float)(EMD_B * EMD_N))

#define SCAN_T    1024
#define SCAN_BLKS (TOT2 / SCAN_T)    // 2048

__device__ int    g_cnt[TOT2];
__device__ int    g_cur[TOT2];
__device__ int    g_off[TOT2];
__device__ int    g_bsum[SCAN_BLKS];
__device__ float4 g_tpts[NPTS];      // binned targets (x,y,z,t2)
__device__ float4 g_spred[NPTS];     // Morton-sorted preds
__device__ int    g_fail[NPTS];
__device__ int    g_nfail;

__device__ __forceinline__ int cell_of(float v)
{
    int c = (int)floorf((v - XMIN) * INVH);
    return min(max(c, 0), G - 1);
}

__device__ __forceinline__ unsigned ex5(unsigned v)  // spread 5 bits to every 3rd
{
    v = (v | (v << 8)) & 0x100Fu;
    v = (v | (v << 4)) & 0x10C3u;
    v = (v | (v << 2)) & 0x1249u;
    return v;
}

// ---------------------------------------------------------------- zero
__global__ void __launch_bounds__(256)
zero_kernel()
{
    const int i = blockIdx.x * 256 + threadIdx.x;
    g_cnt[i] = 0;
    g_cur[i] = 0;
    if (i == 0) g_nfail = 0;
}

// ---------------------------------------------------------------- count (targets + preds)
__global__ void __launch_bounds__(256)
count_kernel(const float* __restrict__ pred, const float* __restrict__ target)
{
    const int i = blockIdx.x * 256 + threadIdx.x;     // 0 .. 2*NPTS-1
    int idx;
    if (i < NPTS) {
        const int b = i >> 12;
        const float* t = target + (size_t)i * 3;
        idx = b * NCELLS + (cell_of(t[2]) * G + cell_of(t[1])) * G + cell_of(t[0]);
    } else {
        const int j = i - NPTS;
        const int b = j >> 12;
        const float* p = pred + (size_t)j * 3;
        const unsigned mort = ex5(cell_of(p[0])) | (ex5(cell_of(p[1])) << 1)
                            | (ex5(cell_of(p[2])) << 2);
        idx = TCELLS + b * NCELLS + (int)mort;
    }
    atomicAdd(&g_cnt[idx], 1);
}

// ---------------------------------------------------------------- scan A
__global__ void __launch_bounds__(SCAN_T)
scanA_kernel()
{
    __shared__ int sh[SCAN_T];
    const int t = threadIdx.x;
    const int i = blockIdx.x * SCAN_T + t;
    const int v = g_cnt[i];
    sh[t] = v;
    __syncthreads();
    #pragma unroll
    for (int off = 1; off < SCAN_T; off <<= 1) {
        int u = (t >= off) ? sh[t - off] : 0;
        __syncthreads();
        sh[t] += u;
        __syncthreads();
    }
    g_off[i] = sh[t] - v;
    if (t == SCAN_T - 1) g_bsum[blockIdx.x] = sh[t];
}

// ---------------------------------------------------------------- scan B (2048 sums, 1024 thr)
__global__ void __launch_bounds__(SCAN_T)
scanB_kernel()
{
    __shared__ int sh[SCAN_T];
    const int t = threadIdx.x;
    const int v0 = g_bsum[2 * t];
    const int v1 = g_bsum[2 * t + 1];
    const int s = v0 + v1;
    sh[t] = s;
    __syncthreads();
    #pragma unroll
    for (int off = 1; off < SCAN_T; off <<= 1) {
        int u = (t >= off) ? sh[t - off] : 0;
        __syncthreads();
        sh[t] += u;
        __syncthreads();
    }
    const int ex = sh[t] - s;
    g_bsum[2 * t]     = ex;
    g_bsum[2 * t + 1] = ex + v0;
}

// ---------------------------------------------------------------- scan C
__global__ void __launch_bounds__(SCAN_T)
scanC_kernel()
{
    const int i = blockIdx.x * SCAN_T + threadIdx.x;
    g_off[i] += g_bsum[blockIdx.x];
}

// ---------------------------------------------------------------- scatter (targets + preds)
__global__ void __launch_bounds__(256)
scatter_kernel(const float* __restrict__ pred, const float* __restrict__ target)
{
    const int i = blockIdx.x * 256 + threadIdx.x;
    if (i < NPTS) {
        const int b = i >> 12;
        const float* t = target + (size_t)i * 3;
        const float x = t[0], y = t[1], z = t[2];
        const int idx = b * NCELLS + (cell_of(z) * G + cell_of(y)) * G + cell_of(x);
        const int slot = g_off[idx] + atomicAdd(&g_cur[idx], 1);
        g_tpts[slot] = make_float4(x, y, z, fmaf(x, x, fmaf(y, y, z * z)));
    } else {
        const int j = i - NPTS;
        const int b = j >> 12;
        const float* p = pred + (size_t)j * 3;
        const float x = p[0], y = p[1], z = p[2];
        const unsigned mort = ex5(cell_of(x)) | (ex5(cell_of(y)) << 1)
                            | (ex5(cell_of(z)) << 2);
        const int idx = TCELLS + b * NCELLS + (int)mort;
        const int slot = g_off[idx] - NPTS + atomicAdd(&g_cur[idx], 1);
        g_spred[slot] = make_float4(x, y, z, 0.0f);
    }
}

// ---------------------------------------------------------------- pass 1: coherent warp scan
__global__ void __launch_bounds__(256)
pass1_kernel(float* __restrict__ out)
{
    __shared__ float shsum[8];

    const int lane = threadIdx.x & 31;
    const int wid  = threadIdx.x >> 5;
    const int i    = blockIdx.x * 256 + threadIdx.x;   // sorted pred index
    const int b    = i >> 12;                          // warps never span batches

    const float4 P = g_spred[i];
    const float px = P.x, py = P.y, pz = P.z;
    const float qx = -2.0f * px, qy = -2.0f * py, qz = -2.0f * pz;
    const float p2 = fmaf(px, px, fmaf(py, py, pz * pz));
    const int cx = cell_of(px), cy = cell_of(py), cz = cell_of(pz);

    const int xlo = max(__reduce_min_sync(0xffffffffu, cx) - 1, 0);
    const int xhi = min(__reduce_max_sync(0xffffffffu, cx) + 1, G - 1);
    const int ylo = max(__reduce_min_sync(0xffffffffu, cy) - 1, 0);
    const int yhi = min(__reduce_max_sync(0xffffffffu, cy) + 1, G - 1);
    const int zlo = max(__reduce_min_sync(0xffffffffu, cz) - 1, 0);
    const int zhi = min(__reduce_max_sync(0xffffffffu, cz) + 1, G - 1);

    const int vol = (xhi - xlo + 1) * (yhi - ylo + 1) * (zhi - zlo + 1);

    float best = 3.4e38f;   // min of s = t2 - 2 p.t

    if (vol <= VOLCAP) {
        const int bbase = b * NCELLS;
        for (int z = zlo; z <= zhi; z++) {
            for (int y = ylo; y <= yhi; y++) {
                const int rb = bbase + (z * G + y) * G;
                for (int x = xlo; x <= xhi; x++) {
                    const int c   = rb + x;
                    const int off = __ldg(&g_off[c]);   // broadcast
                    const int cnt = __ldg(&g_cnt[c]);
                    for (int t = 0; t < cnt; t++) {
                        const float4 q = __ldg(&g_tpts[off + t]);   // broadcast
                        const float s = fmaf(qx, q.x, fmaf(qy, q.y, fmaf(qz, q.z, q.w)));
                        best = fminf(best, s);
                    }
                }
            }
        }
    }

    const float d2 = fmaxf(p2 + best, 0.0f);

    // exact stop bound: nearest non-clipped face plane of the scanned bbox
    float bnd = 3.4e38f;
    if (xlo > 0)     bnd = fminf(bnd, px - (XMIN + (float)xlo * H));
    if (xhi < G - 1) bnd = fminf(bnd, (XMIN + (float)(xhi + 1) * H) - px);
    if (ylo > 0)     bnd = fminf(bnd, py - (XMIN + (float)ylo * H));
    if (yhi < G - 1) bnd = fminf(bnd, (XMIN + (float)(yhi + 1) * H) - py);
    if (zlo > 0)     bnd = fminf(bnd, pz - (XMIN + (float)zlo * H));
    if (zhi < G - 1) bnd = fminf(bnd, (XMIN + (float)(zhi + 1) * H) - pz);
    bnd = fmaxf(bnd, 0.0f);

    const bool ok = (vol <= VOLCAP) && (best < 3.4e38f) && (d2 <= bnd * bnd);

    float val = ok ? sqrtf(d2) * INVTOT : 0.0f;

    // append failures (warp-aggregated)
    const unsigned m = __ballot_sync(0xffffffffu, !ok);
    int base = 0;
    if (m) {
        const int leader = __ffs(m) - 1;
        if (lane == leader) base = atomicAdd(&g_nfail, __popc(m));
        base = __shfl_sync(0xffffffffu, base, leader);
        if (!ok) g_fail[base + __popc(m & ((1u << lane) - 1))] = i;
    }

    #pragma unroll
    for (int o = 16; o; o >>= 1)
        val += __shfl_xor_sync(0xffffffffu, val, o);
    if (lane == 0) shsum[wid] = val;
    __syncthreads();
    if (threadIdx.x < 8) {
        float v = shsum[threadIdx.x];
        #pragma unroll
        for (int o = 4; o; o >>= 1)
            v += __shfl_xor_sync(0xffu, v, o);
        if (threadIdx.x == 0) atomicAdd(out, v);
    }
}

// ---------------------------------------------------------------- pass 2: brute for failures
__global__ void __launch_bounds__(256)
pass2_kernel(float* __restrict__ out)
{
    __shared__ float shsum[8];

    const int j = blockIdx.x * 256 + threadIdx.x;
    const int n = g_nfail;
    float val = 0.0f;

    if (j < n) {
        const int i = g_fail[j];
        const int b = i >> 12;
        const float4 P = g_spred[i];
        const float qx = -2.0f * P.x, qy = -2.0f * P.y, qz = -2.0f * P.z;
        const float p2 = fmaf(P.x, P.x, fmaf(P.y, P.y, P.z * P.z));

        const float4* __restrict__ tp = g_tpts + (size_t)b * EMD_M;
        float m0 = 3.4e38f, m1 = 3.4e38f;
        #pragma unroll 4
        for (int t = 0; t < EMD_M; t += 2) {
            const float4 q0 = __ldg(tp + t);
            const float4 q1 = __ldg(tp + t + 1);
            const float s0 = fmaf(qx, q0.x, fmaf(qy, q0.y, fmaf(qz, q0.z, q0.w)));
            const float s1 = fmaf(qx, q1.x, fmaf(qy, q1.y, fmaf(qz, q1.z, q1.w)));
            m0 = fminf(m0, s0);
            m1 = fminf(m1, s1);
        }
        val = sqrtf(fmaxf(p2 + fminf(m0, m1), 0.0f)) * INVTOT;
    }

    #pragma unroll
    for (int o = 16; o; o >>= 1)
        val += __shfl_xor_sync(0xffffffffu, val, o);
    if ((threadIdx.x & 31) == 0) shsum[threadIdx.x >> 5] = val;
    __syncthreads();
    if (threadIdx.x < 8) {
        float v = shsum[threadIdx.x];
        #pragma unroll
        for (int o = 4; o; o >>= 1)
            v += __shfl_xor_sync(0xffu, v, o);
        if (threadIdx.x == 0) atomicAdd(out, v);
    }
}

extern "C" void kernel_launch(void* const* d_in, const int* in_sizes, int n_in,
                              void* d_out, int out_size)
{
    const float* pred   = (const float*)d_in[0];
    const float* target = (const float*)d_in[1];
    float* out = (float*)d_out;

    cudaMemsetAsync(out, 0, sizeof(float));

    zero_kernel<<<TOT2 / 256, 256>>>();
    count_kernel<<<2 * NPTS / 256, 256>>>(pred, target);
    scanA_kernel<<<SCAN_BLKS, SCAN_T>>>();
    scanB_kernel<<<1, SCAN_T>>>();
    scanC_kernel<<<SCAN_BLKS, SCAN_T>>>();
    scatter_kernel<<<2 * NPTS / 256, 256>>>(pred, target);
    pass1_kernel<<<NPTS / 256, 256>>>(out);
    pass2_kernel<<<NPTS / 256, 256>>>(out);
}

// round 12
// speedup vs baseline: 1.7922x; 1.7922x over previous
#include <cuda_runtime.h>
#include <cuda_bf16.h>
#include <math.h>

// EMDLoss: mean over (b,n) of min_m ||pred[b,n]-target[b,m]||, B=32, N=M=4096, d=3.
// Exact grid-pruned NN with brute-force-structured inner loop:
//   targets raster-binned (CSR), preds Morton-binned (counting sort => warp/block
//   spatial coherence). Main kernel: block of 256 adjacent preds stages all targets
//   in its (bbox+1) cell neighborhood into smem, then each thread runs a tight
//   unrolled loop over the staged candidates. Exact per-pred stopping bound =
//   distance to nearest non-clipped face of the staged bbox (clipped faces => inf,
//   which also covers out-of-range points clamped into boundary cells).
//   Failures fall back to brute force over the batch's 4096 binned targets.

#define EMD_B 32
#define EMD_N 4096
#define EMD_M 4096

#define G      32
#define NCELLS (G * G * G)           // 32768 per batch
#define TCELLS (EMD_B * NCELLS)      // 1,048,576 per side
#define TOT2   (2 * TCELLS)
#define XMIN   (-4.0f)
#define H      0.25f
#define INVH   4.0f

#define NPTS   (EMD_B * EMD_M)       // 131072
#define INVTOT (1.0f / (float)(EMD_B * EMD_N))

#define SCAN_T    1024
#define SCAN_BLKS (TOT2 / SCAN_T)    // 2048

#define MAIN_T 256
#define SMAX   2048                  // staged candidate cap (32 KB)
#define VOLCAP 1000

__device__ int    g_cnt[TOT2];
__device__ int    g_off[TOT2];
__device__ int    g_bsum[SCAN_BLKS];
__device__ float4 g_tpts[NPTS];      // binned targets (x,y,z,t2)
__device__ float4 g_spred[NPTS];     // Morton-sorted preds

__device__ __forceinline__ int cell_of(float v)
{
    int c = (int)floorf((v - XMIN) * INVH);
    return min(max(c, 0), G - 1);
}

__device__ __forceinline__ unsigned ex5(unsigned v)  // spread 5 bits to every 3rd
{
    v = (v | (v << 8)) & 0x100Fu;
    v = (v | (v << 4)) & 0x10C3u;
    v = (v | (v << 2)) & 0x1249u;
    return v;
}

// ---------------------------------------------------------------- count (targets + preds)
__global__ void __launch_bounds__(256)
count_kernel(const float* __restrict__ pred, const float* __restrict__ target)
{
    const int i = blockIdx.x * 256 + threadIdx.x;     // 0 .. 2*NPTS-1
    int idx;
    if (i < NPTS) {
        const int b = i >> 12;
        const float* t = target + (size_t)i * 3;
        idx = b * NCELLS + (cell_of(t[2]) * G + cell_of(t[1])) * G + cell_of(t[0]);
    } else {
        const int j = i - NPTS;
        const int b = j >> 12;
        const float* p = pred + (size_t)j * 3;
        const unsigned mort = ex5(cell_of(p[0])) | (ex5(cell_of(p[1])) << 1)
                            | (ex5(cell_of(p[2])) << 2);
        idx = TCELLS + b * NCELLS + (int)mort;
    }
    atomicAdd(&g_cnt[idx], 1);
}

// ---------------------------------------------------------------- scan A
__global__ void __launch_bounds__(SCAN_T)
scanA_kernel()
{
    __shared__ int sh[SCAN_T];
    const int t = threadIdx.x;
    const int i = blockIdx.x * SCAN_T + t;
    const int v = g_cnt[i];
    sh[t] = v;
    __syncthreads();
    #pragma unroll
    for (int off = 1; off < SCAN_T; off <<= 1) {
        int u = (t >= off) ? sh[t - off] : 0;
        __syncthreads();
        sh[t] += u;
        __syncthreads();
    }
    g_off[i] = sh[t] - v;
    if (t == SCAN_T - 1) g_bsum[blockIdx.x] = sh[t];
}

// ---------------------------------------------------------------- scan B (2048 sums)
__global__ void __launch_bounds__(SCAN_T)
scanB_kernel()
{
    __shared__ int sh[SCAN_T];
    const int t = threadIdx.x;
    const int v0 = g_bsum[2 * t];
    const int v1 = g_bsum[2 * t + 1];
    const int s = v0 + v1;
    sh[t] = s;
    __syncthreads();
    #pragma unroll
    for (int off = 1; off < SCAN_T; off <<= 1) {
        int u = (t >= off) ? sh[t - off] : 0;
        __syncthreads();
        sh[t] += u;
        __syncthreads();
    }
    const int ex = sh[t] - s;
    g_bsum[2 * t]     = ex;
    g_bsum[2 * t + 1] = ex + v0;
}

// ---------------------------------------------------------------- scan C
__global__ void __launch_bounds__(SCAN_T)
scanC_kernel()
{
    const int i = blockIdx.x * SCAN_T + threadIdx.x;
    g_off[i] += g_bsum[blockIdx.x];
}

// ---------------------------------------------------------------- scatter (mutates g_off: +cnt)
__global__ void __launch_bounds__(256)
scatter_kernel(const float* __restrict__ pred, const float* __restrict__ target)
{
    const int i = blockIdx.x * 256 + threadIdx.x;
    if (i < NPTS) {
        const int b = i >> 12;
        const float* t = target + (size_t)i * 3;
        const float x = t[0], y = t[1], z = t[2];
        const int idx = b * NCELLS + (cell_of(z) * G + cell_of(y)) * G + cell_of(x);
        const int slot = atomicAdd(&g_off[idx], 1);
        g_tpts[slot] = make_float4(x, y, z, fmaf(x, x, fmaf(y, y, z * z)));
    } else {
        const int j = i - NPTS;
        const int b = j >> 12;
        const float* p = pred + (size_t)j * 3;
        const float x = p[0], y = p[1], z = p[2];
        const unsigned mort = ex5(cell_of(x)) | (ex5(cell_of(y)) << 1)
                            | (ex5(cell_of(z)) << 2);
        const int idx = TCELLS + b * NCELLS + (int)mort;
        const int slot = atomicAdd(&g_off[idx], 1) - NPTS;
        g_spred[slot] = make_float4(x, y, z, 0.0f);
    }
}
// after scatter: g_off[c] = start(c) + cnt(c)  => start = g_off[c] - g_cnt[c]

// ---------------------------------------------------------------- main
__global__ void __launch_bounds__(MAIN_T)
main_kernel(float* __restrict__ out)
{
    __shared__ float4 scand[SMAX];
    __shared__ int    s_n;
    __shared__ int    s_bb[6];          // minx,miny,minz,maxx,maxy,maxz
    __shared__ float  ssum[MAIN_T / 32];

    const int tid  = threadIdx.x;
    const int lane = tid & 31;
    const int i    = blockIdx.x * MAIN_T + tid;   // sorted pred index
    const int b    = i >> 12;                     // block never spans batches

    const float4 P = g_spred[i];
    const float px = P.x, py = P.y, pz = P.z;
    const float qx = -2.0f * px, qy = -2.0f * py, qz = -2.0f * pz;
    const float p2 = fmaf(px, px, fmaf(py, py, pz * pz));
    const int cx = cell_of(px), cy = cell_of(py), cz = cell_of(pz);

    if (tid == 0) {
        s_n = 0;
        s_bb[0] = G; s_bb[1] = G; s_bb[2] = G;
        s_bb[3] = -1; s_bb[4] = -1; s_bb[5] = -1;
    }
    __syncthreads();

    // block bbox over pred cells (warp reduce, then smem atomics)
    {
        const int mnx = __reduce_min_sync(0xffffffffu, cx);
        const int mny = __reduce_min_sync(0xffffffffu, cy);
        const int mnz = __reduce_min_sync(0xffffffffu, cz);
        const int mxx = __reduce_max_sync(0xffffffffu, cx);
        const int mxy = __reduce_max_sync(0xffffffffu, cy);
        const int mxz = __reduce_max_sync(0xffffffffu, cz);
        if (lane == 0) {
            atomicMin(&s_bb[0], mnx); atomicMin(&s_bb[1], mny); atomicMin(&s_bb[2], mnz);
            atomicMax(&s_bb[3], mxx); atomicMax(&s_bb[4], mxy); atomicMax(&s_bb[5], mxz);
        }
    }
    __syncthreads();

    const int xlo = max(s_bb[0] - 1, 0), xhi = min(s_bb[3] + 1, G - 1);
    const int ylo = max(s_bb[1] - 1, 0), yhi = min(s_bb[4] + 1, G - 1);
    const int zlo = max(s_bb[2] - 1, 0), zhi = min(s_bb[5] + 1, G - 1);
    const int xs = xhi - xlo + 1, ys = yhi - ylo + 1, zs = zhi - zlo + 1;
    const int vol = xs * ys * zs;

    // cooperative staging of all targets in the bbox
    if (vol <= VOLCAP) {
        const int bbase = b * NCELLS;
        for (int c = tid; c < vol; c += MAIN_T) {
            const int dz = c / (xs * ys);
            const int r  = c - dz * (xs * ys);
            const int dy = r / xs;
            const int dx = r - dy * xs;
            const int cell = bbase + ((zlo + dz) * G + (ylo + dy)) * G + (xlo + dx);
            const int cnt = g_cnt[cell];
            if (cnt) {
                const int start = g_off[cell] - cnt;
                const int pos = atomicAdd(&s_n, cnt);
                if (pos + cnt <= SMAX) {
                    for (int t = 0; t < cnt; t++)
                        scand[pos + t] = g_tpts[start + t];
                }
            }
        }
    }
    __syncthreads();

    const int S = s_n;
    const bool blockOK = (vol <= VOLCAP) && (S <= SMAX);

    float best = 3.4e38f;           // min of s = t2 - 2 p.t
    bool ok = false;

    if (blockOK) {
        float m0 = 3.4e38f, m1 = 3.4e38f;
        int t = 0;
        #pragma unroll 4
        for (; t + 1 < S; t += 2) {
            const float4 q0 = scand[t];
            const float4 q1 = scand[t + 1];
            m0 = fminf(m0, fmaf(qx, q0.x, fmaf(qy, q0.y, fmaf(qz, q0.z, q0.w))));
            m1 = fminf(m1, fmaf(qx, q1.x, fmaf(qy, q1.y, fmaf(qz, q1.z, q1.w))));
        }
        if (t < S) {
            const float4 q = scand[t];
            m0 = fminf(m0, fmaf(qx, q.x, fmaf(qy, q.y, fmaf(qz, q.z, q.w))));
        }
        best = fminf(m0, m1);

        // exact stopping bound: nearest non-clipped face plane of staged bbox
        float bnd = 3.4e38f;
        if (xlo > 0)     bnd = fminf(bnd, px - (XMIN + (float)xlo * H));
        if (xhi < G - 1) bnd = fminf(bnd, (XMIN + (float)(xhi + 1) * H) - px);
        if (ylo > 0)     bnd = fminf(bnd, py - (XMIN + (float)ylo * H));
        if (yhi < G - 1) bnd = fminf(bnd, (XMIN + (float)(yhi + 1) * H) - py);
        if (zlo > 0)     bnd = fminf(bnd, pz - (XMIN + (float)zlo * H));
        if (zhi < G - 1) bnd = fminf(bnd, (XMIN + (float)(zhi + 1) * H) - pz);
        bnd = fmaxf(bnd, 0.0f);
        ok = (fmaxf(p2 + best, 0.0f) <= bnd * bnd);
    }

    // fallback: brute force over this batch's 4096 binned targets
    if (__ballot_sync(0xffffffffu, !ok)) {
        if (!ok) {
            const float4* __restrict__ tp = g_tpts + (size_t)b * EMD_M;
            float m0 = 3.4e38f, m1 = 3.4e38f;
            #pragma unroll 4
            for (int t = 0; t < EMD_M; t += 2) {
                const float4 q0 = __ldg(tp + t);
                const float4 q1 = __ldg(tp + t + 1);
                m0 = fminf(m0, fmaf(qx, q0.x, fmaf(qy, q0.y, fmaf(qz, q0.z, q0.w))));
                m1 = fminf(m1, fmaf(qx, q1.x, fmaf(qy, q1.y, fmaf(qz, q1.z, q1.w))));
            }
            best = fminf(m0, m1);
        }
    }

    float val = sqrtf(fmaxf(p2 + best, 0.0f)) * INVTOT;

    #pragma unroll
    for (int o = 16; o; o >>= 1)
        val += __shfl_xor_sync(0xffffffffu, val, o);
    if (lane == 0) ssum[tid >> 5] = val;
    __syncthreads();
    if (tid < (MAIN_T / 32)) {
        float v = ssum[tid];
        #pragma unroll
        for (int o = (MAIN_T / 64); o; o >>= 1)
            v += __shfl_xor_sync(0xffu, v, o);
        if (tid == 0) atomicAdd(out, v);
    }
}

extern "C" void kernel_launch(void* const* d_in, const int* in_sizes, int n_in,
                              void* d_out, int out_size)
{
    const float* pred   = (const float*)d_in[0];
    const float* target = (const float*)d_in[1];
    float* out = (float*)d_out;

    cudaMemsetAsync(out, 0, sizeof(float));

    void* cnt_addr = nullptr;
    cudaGetSymbolAddress(&cnt_addr, g_cnt);
    cudaMemsetAsync(cnt_addr, 0, (size_t)TOT2 * sizeof(int));

    count_kernel<<<2 * NPTS / 256, 256>>>(pred, target);
    scanA_kernel<<<SCAN_BLKS, SCAN_T>>>();
    scanB_kernel<<<1, SCAN_T>>>();
    scanC_kernel<<<SCAN_BLKS, SCAN_T>>>();
    scatter_kernel<<<2 * NPTS / 256, 256>>>(pred, target);
    main_kernel<<<NPTS / MAIN_T, MAIN_T>>>(out);
}

// round 14
// speedup vs baseline: 3.2047x; 1.7881x over previous
#include <cuda_runtime.h>
#include <cuda_bf16.h>
#include <math.h>

// EMDLoss: mean over (b,n) of min_m ||pred[b,n]-target[b,m]||, B=32, N=M=4096, d=3.
// Exact warp-granular grid-pruned NN:
//   targets: CSR over fine 32^3 raster per batch (out-of-range clamps to boundary cells).
//   preds:   counting-sorted by Morton over a COARSE 16^3 bucket grid per batch,
//            so each warp's 32 preds form a compact spatial blob.
//   main:    per warp: bbox(pred cells)+1 ring; lane-parallel staging of all targets
//            in the bbox into a per-warp smem buffer (independent loads -> MLP);
//            then an R2-style tight broadcast loop over S staged candidates.
//            Exact stop bound: nearest non-clipped bbox face plane (clipped => inf).
//   pass2:   failed / over-cap preds -> warp per pred, lanes split 4096 targets.

#define EMD_B 32
#define EMD_N 4096
#define EMD_M 4096

#define G      32
#define NCELLS (G * G * G)                 // 32768 fine cells per batch
#define TCELLS (EMD_B * NCELLS)            // 1,048,576 target cells
#define PBUCK  4096                        // 16^3 coarse pred buckets per batch
#define TPBUCK (EMD_B * PBUCK)             // 131,072 pred buckets
#define TOTC   (TCELLS + TPBUCK)           // 1,179,648 combined scan domain
#define XMIN   (-4.0f)
#define H      0.25f
#define INVH   4.0f

#define NPTS   (EMD_B * EMD_M)             // 131072
#define INVTOT (1.0f / (float)(EMD_B * EMD_N))

#define SCAN_T    1024
#define SCAN_BLKS (TOTC / SCAN_T)          // 1152
#define SCANB_T   576                      // 1152 / 2

#define MAIN_T 128                         // 4 warps
#define SWCAP  512                         // staged candidates per warp (8 KB)
#define VOLCAP 512

__device__ int    g_cnt[TOTC];
__device__ int    g_off[TOTC];
__device__ int    g_bsum[SCAN_BLKS];
__device__ float4 g_tpts[NPTS];            // binned targets (x,y,z,t2)
__device__ float4 g_spred[NPTS];           // Morton-bucket-sorted preds
__device__ int    g_fail[NPTS];
__device__ int    g_nfail;

__device__ __forceinline__ int cell_of(float v)
{
    int c = (int)floorf((v - XMIN) * INVH);
    return min(max(c, 0), G - 1);
}

__device__ __forceinline__ unsigned ex5(unsigned v)  // spread low 5 bits to every 3rd
{
    v = (v | (v << 8)) & 0x100Fu;
    v = (v | (v << 4)) & 0x10C3u;
    v = (v | (v << 2)) & 0x1249u;
    return v;
}

// ---------------------------------------------------------------- zero nfail
__global__ void zero_kernel() { g_nfail = 0; }

// ---------------------------------------------------------------- count
__global__ void __launch_bounds__(256)
count_kernel(const float* __restrict__ pred, const float* __restrict__ target)
{
    const int i = blockIdx.x * 256 + threadIdx.x;     // 0 .. 2*NPTS-1
    int idx;
    if (i < NPTS) {
        const int b = i >> 12;
        const float* t = target + (size_t)i * 3;
        idx = b * NCELLS + (cell_of(t[2]) * G + cell_of(t[1])) * G + cell_of(t[0]);
    } else {
        const int j = i - NPTS;
        const int b = j >> 12;
        const float* p = pred + (size_t)j * 3;
        const unsigned bx = cell_of(p[0]) >> 1;       // coarse 16^3 coords
        const unsigned by = cell_of(p[1]) >> 1;
        const unsigned bz = cell_of(p[2]) >> 1;
        const unsigned mort = ex5(bx) | (ex5(by) << 1) | (ex5(bz) << 2);  // < 4096
        idx = TCELLS + b * PBUCK + (int)mort;
    }
    atomicAdd(&g_cnt[idx], 1);
}

// ---------------------------------------------------------------- scan A
__global__ void __launch_bounds__(SCAN_T)
scanA_kernel()
{
    __shared__ int sh[SCAN_T];
    const int t = threadIdx.x;
    const int i = blockIdx.x * SCAN_T + t;
    const int v = g_cnt[i];
    sh[t] = v;
    __syncthreads();
    #pragma unroll
    for (int off = 1; off < SCAN_T; off <<= 1) {
        int u = (t >= off) ? sh[t - off] : 0;
        __syncthreads();
        sh[t] += u;
        __syncthreads();
    }
    g_off[i] = sh[t] - v;
    if (t == SCAN_T - 1) g_bsum[blockIdx.x] = sh[t];
}

// ---------------------------------------------------------------- scan B (1152 sums, 576 thr)
__global__ void __launch_bounds__(SCANB_T)
scanB_kernel()
{
    __shared__ int sh[SCANB_T];
    const int t = threadIdx.x;
    const int v0 = g_bsum[2 * t];
    const int v1 = g_bsum[2 * t + 1];
    const int s = v0 + v1;
    sh[t] = s;
    __syncthreads();
    for (int off = 1; off < SCANB_T; off <<= 1) {
        int u = (t >= off) ? sh[t - off] : 0;
        __syncthreads();
        sh[t] += u;
        __syncthreads();
    }
    const int ex = sh[t] - s;
    g_bsum[2 * t]     = ex;
    g_bsum[2 * t + 1] = ex + v0;
}

// ---------------------------------------------------------------- scan C
__global__ void __launch_bounds__(SCAN_T)
scanC_kernel()
{
    const int i = blockIdx.x * SCAN_T + threadIdx.x;
    g_off[i] += g_bsum[blockIdx.x];
}

// ---------------------------------------------------------------- scatter (mutates g_off += cnt)
__global__ void __launch_bounds__(256)
scatter_kernel(const float* __restrict__ pred, const float* __restrict__ target)
{
    const int i = blockIdx.x * 256 + threadIdx.x;
    if (i < NPTS) {
        const int b = i >> 12;
        const float* t = target + (size_t)i * 3;
        const float x = t[0], y = t[1], z = t[2];
        const int idx = b * NCELLS + (cell_of(z) * G + cell_of(y)) * G + cell_of(x);
        const int slot = atomicAdd(&g_off[idx], 1);
        g_tpts[slot] = make_float4(x, y, z, fmaf(x, x, fmaf(y, y, z * z)));
    } else {
        const int j = i - NPTS;
        const int b = j >> 12;
        const float* p = pred + (size_t)j * 3;
        const float x = p[0], y = p[1], z = p[2];
        const unsigned mort = ex5(cell_of(x) >> 1) | (ex5(cell_of(y) >> 1) << 1)
                            | (ex5(cell_of(z) >> 1) << 2);
        const int idx = TCELLS + b * PBUCK + (int)mort;
        const int slot = atomicAdd(&g_off[idx], 1) - NPTS;
        g_spred[slot] = make_float4(x, y, z, 0.0f);
    }
}
// after scatter: start(c) = g_off[c] - g_cnt[c]

// ---------------------------------------------------------------- main: warp-granular staging
__global__ void __launch_bounds__(MAIN_T)
main_kernel(float* __restrict__ out)
{
    __shared__ float4 swarp[(MAIN_T / 32) * SWCAP];   // 32 KB
    __shared__ float  ssum[MAIN_T / 32];

    const int tid  = threadIdx.x;
    const int lane = tid & 31;
    const int wid  = tid >> 5;
    const int i    = blockIdx.x * MAIN_T + tid;       // sorted pred index
    const int b    = i >> 12;                         // warps never span batches

    const float4 P = g_spred[i];
    const float px = P.x, py = P.y, pz = P.z;
    const float qx = -2.0f * px, qy = -2.0f * py, qz = -2.0f * pz;
    const float p2 = fmaf(px, px, fmaf(py, py, pz * pz));
    const int cx = cell_of(px), cy = cell_of(py), cz = cell_of(pz);

    // warp bbox over pred cells, +1 ring, clipped
    const int xlo = max(__reduce_min_sync(0xffffffffu, cx) - 1, 0);
    const int xhi = min(__reduce_max_sync(0xffffffffu, cx) + 1, G - 1);
    const int ylo = max(__reduce_min_sync(0xffffffffu, cy) - 1, 0);
    const int yhi = min(__reduce_max_sync(0xffffffffu, cy) + 1, G - 1);
    const int zlo = max(__reduce_min_sync(0xffffffffu, cz) - 1, 0);
    const int zhi = min(__reduce_max_sync(0xffffffffu, cz) + 1, G - 1);
    const int xs = xhi - xlo + 1, ys = yhi - ylo + 1, zs = zhi - zlo + 1;
    const int vol = xs * ys * zs;

    float4* sw = swarp + wid * SWCAP;
    int S = 0;

    if (vol <= VOLCAP) {
        const int bbase = b * NCELLS;
        for (int c0 = 0; c0 < vol; c0 += 32) {
            const int c = c0 + lane;
            int cnt = 0, start = 0;
            if (c < vol) {
                const int dz = c / (xs * ys);
                const int r  = c - dz * (xs * ys);
                const int dy = r / xs;
                const int dx = r - dy * xs;
                const int cell = bbase + ((zlo + dz) * G + (ylo + dy)) * G + (xlo + dx);
                cnt   = g_cnt[cell];
                start = g_off[cell] - cnt;
            }
            // warp exclusive scan of cnt
            int pos = cnt;
            #pragma unroll
            for (int o = 1; o < 32; o <<= 1) {
                const int u = __shfl_up_sync(0xffffffffu, pos, o);
                if (lane >= o) pos += u;
            }
            const int tot = __shfl_sync(0xffffffffu, pos, 31);
            pos -= cnt;
            if (S + tot <= SWCAP) {
                for (int t = 0; t < cnt; t++)
                    sw[S + pos + t] = g_tpts[start + t];
            }
            S += tot;
        }
    }
    __syncwarp();

    const bool over = (vol > VOLCAP) || (S > SWCAP);

    float best = 3.4e38f;           // min of s = t2 - 2 p.t
    if (!over) {
        float m0 = 3.4e38f, m1 = 3.4e38f;
        int t = 0;
        #pragma unroll 4
        for (; t + 1 < S; t += 2) {
            const float4 q0 = sw[t];
            const float4 q1 = sw[t + 1];
            m0 = fminf(m0, fmaf(qx, q0.x, fmaf(qy, q0.y, fmaf(qz, q0.z, q0.w))));
            m1 = fminf(m1, fmaf(qx, q1.x, fmaf(qy, q1.y, fmaf(qz, q1.z, q1.w))));
        }
        if (t < S) {
            const float4 q = sw[t];
            m0 = fminf(m0, fmaf(qx, q.x, fmaf(qy, q.y, fmaf(qz, q.z, q.w))));
        }
        best = fminf(m0, m1);
    }

    const float d2 = fmaxf(p2 + best, 0.0f);

    // exact stop bound: nearest non-clipped face plane of the staged bbox
    float bnd = 3.4e38f;
    if (xlo > 0)     bnd = fminf(bnd, px - (XMIN + (float)xlo * H));
    if (xhi < G - 1) bnd = fminf(bnd, (XMIN + (float)(xhi + 1) * H) - px);
    if (ylo > 0)     bnd = fminf(bnd, py - (XMIN + (float)ylo * H));
    if (yhi < G - 1) bnd = fminf(bnd, (XMIN + (float)(yhi + 1) * H) - py);
    if (zlo > 0)     bnd = fminf(bnd, pz - (XMIN + (float)zlo * H));
    if (zhi < G - 1) bnd = fminf(bnd, (XMIN + (float)(zhi + 1) * H) - pz);
    bnd = fmaxf(bnd, 0.0f);

    const bool fail = over || !(d2 <= bnd * bnd);

    // warp-aggregated failure append
    const unsigned m = __ballot_sync(0xffffffffu, fail);
    if (m) {
        const int leader = __ffs(m) - 1;
        int base = 0;
        if (lane == leader) base = atomicAdd(&g_nfail, __popc(m));
        base = __shfl_sync(0xffffffffu, base, leader);
        if (fail) g_fail[base + __popc(m & ((1u << lane) - 1))] = i;
    }

    float val = fail ? 0.0f : sqrtf(d2) * INVTOT;

    #pragma unroll
    for (int o = 16; o; o >>= 1)
        val += __shfl_xor_sync(0xffffffffu, val, o);
    if (lane == 0) ssum[wid] = val;
    __syncthreads();
    if (tid < (MAIN_T / 32)) {
        float v = ssum[tid];
        #pragma unroll
        for (int o = (MAIN_T / 64); o; o >>= 1)
            v += __shfl_xor_sync(0xfu, v, o);
        if (tid == 0) atomicAdd(out, v);
    }
}

// ---------------------------------------------------------------- pass2: warp per failed pred
#define P2_T 256
#define P2_B 512

__global__ void __launch_bounds__(P2_T)
pass2_kernel(float* __restrict__ out)
{
    const int lane = threadIdx.x & 31;
    const int w    = blockIdx.x * (P2_T / 32) + (threadIdx.x >> 5);
    const int wtot = P2_B * (P2_T / 32);
    const int n    = g_nfail;

    float acc = 0.0f;

    for (int j = w; j < n; j += wtot) {
        const int i = g_fail[j];
        const int b = i >> 12;
        const float4 P = g_spred[i];
        const float qx = -2.0f * P.x, qy = -2.0f * P.y, qz = -2.0f * P.z;
        const float p2 = fmaf(P.x, P.x, fmaf(P.y, P.y, P.z * P.z));

        const float4* __restrict__ tp = g_tpts + (size_t)b * EMD_M;
        float m0 = 3.4e38f, m1 = 3.4e38f;
        for (int t = lane; t < EMD_M; t += 64) {
            const float4 q0 = __ldg(tp + t);
            const float4 q1 = __ldg(tp + t + 32);
            m0 = fminf(m0, fmaf(qx, q0.x, fmaf(qy, q0.y, fmaf(qz, q0.z, q0.w))));
            m1 = fminf(m1, fmaf(qx, q1.x, fmaf(qy, q1.y, fmaf(qz, q1.z, q1.w))));
        }
        float mm = fminf(m0, m1);
        #pragma unroll
        for (int o = 16; o; o >>= 1)
            mm = fminf(mm, __shfl_xor_sync(0xffffffffu, mm, o));
        if (lane == 0)
            acc += sqrtf(fmaxf(p2 + mm, 0.0f)) * INVTOT;
    }

    if (lane == 0 && acc != 0.0f)
        atomicAdd(out, acc);
}

extern "C" void kernel_launch(void* const* d_in, const int* in_sizes, int n_in,
                              void* d_out, int out_size)
{
    const float* pred   = (const float*)d_in[0];
    const float* target = (const float*)d_in[1];
    float* out = (float*)d_out;

    cudaMemsetAsync(out, 0, sizeof(float));

    void* cnt_addr = nullptr;
    cudaGetSymbolAddress(&cnt_addr, g_cnt);
    cudaMemsetAsync(cnt_addr, 0, (size_t)TOTC * sizeof(int));

    zero_kernel<<<1, 1>>>();
    count_kernel<<<2 * NPTS / 256, 256>>>(pred, target);
    scanA_kernel<<<SCAN_BLKS, SCAN_T>>>();
    scanB_kernel<<<1, SCANB_T>>>();
    scanC_kernel<<<SCAN_BLKS, SCAN_T>>>();
    scatter_kernel<<<2 * NPTS / 256, 256>>>(pred, target);
    main_kernel<<<NPTS / MAIN_T, MAIN_T>>>(out);
    pass2_kernel<<<P2_B, P2_T>>>(out);
}

// round 16
// speedup vs baseline: 8.6551x; 2.7007x over previous
#include <cuda_runtime.h>
#include <cuda_bf16.h>
#include <math.h>

// EMDLoss: mean over (b,n) of min_m ||pred[b,n]-target[b,m]||, B=32, N=M=4096, d=3.
// Exact row-CSR pruned NN:
//   targets binned by (batch, z-cell, y-cell) row (32x32 rows/batch, raster y-in-z)
//   => any [zlo..zhi]x[ylo..yhi] candidate box is zs CONTIGUOUS memory ranges.
//   preds counting-sorted by serpentine row key for warp spatial coherence.
//   main: warp = 32 adjacent preds; stage the box rows into smem (coalesced),
//   tight broadcast eval loop; exact stop bound = nearest non-clipped y/z face
//   (x unpruned => no x term; clipped faces => inf, covers clamped outliers).
//   Failures -> pass2: warp per pred, brute over batch's 4096 binned targets.

#define EMD_B 32
#define EMD_N 4096
#define EMD_M 4096

#define G      32
#define RPB    (G * G)              // 1024 rows per batch
#define TROWS  (EMD_B * RPB)        // 32768 rows per side
#define XMIN   (-4.0f)
#define H      0.25f
#define INVH   4.0f

#define NPTS   (EMD_B * EMD_M)      // 131072
#define INVTOT (1.0f / (float)(EMD_B * EMD_N))

#define MAIN_T 128                  // 4 warps
#define SWCAP  768                  // staged candidates per warp (12 KB)

__device__ int    g_rcnt[2 * TROWS];     // row counts: targets [0,TROWS), preds [TROWS,2*TROWS)
__device__ int    g_roff[2 * TROWS];     // after scatter: start+cnt
__device__ float4 g_tpts[NPTS];          // row-binned targets (x,y,z,t2)
__device__ float4 g_spred[NPTS];         // row-sorted preds (x,y,z,p2)
__device__ int    g_fail[NPTS];
__device__ int    g_nfail;

__device__ __forceinline__ int cell_of(float v)
{
    int c = (int)floorf((v - XMIN) * INVH);
    return min(max(c, 0), G - 1);
}

// ---------------------------------------------------------------- count
__global__ void __launch_bounds__(256)
count_kernel(const float* __restrict__ pred, const float* __restrict__ target)
{
    const int i = blockIdx.x * 256 + threadIdx.x;     // 0 .. 2*NPTS-1
    int idx;
    if (i < NPTS) {
        const int b = i >> 12;
        const float* t = target + (size_t)i * 3;
        idx = b * RPB + cell_of(t[2]) * G + cell_of(t[1]);
    } else {
        const int j = i - NPTS;
        const int b = j >> 12;
        const float* p = pred + (size_t)j * 3;
        const int cy = cell_of(p[1]);
        const int cz = cell_of(p[2]);
        const int sy = (cz & 1) ? (G - 1 - cy) : cy;   // serpentine
        idx = TROWS + b * RPB + cz * G + sy;
    }
    atomicAdd(&g_rcnt[idx], 1);
}

// ---------------------------------------------------------------- scan: 64 blocks, one per (side,batch)
__global__ void __launch_bounds__(RPB)
scan_kernel()
{
    __shared__ int sh[RPB];
    const int side = blockIdx.x >> 5;
    const int b    = blockIdx.x & 31;
    const int t    = threadIdx.x;
    const int i    = side * TROWS + b * RPB + t;
    const int v    = g_rcnt[i];
    sh[t] = v;
    __syncthreads();
    #pragma unroll
    for (int off = 1; off < RPB; off <<= 1) {
        int u = (t >= off) ? sh[t - off] : 0;
        __syncthreads();
        sh[t] += u;
        __syncthreads();
    }
    g_roff[i] = b * EMD_M + sh[t] - v;    // exclusive prefix + batch base
}

// ---------------------------------------------------------------- scatter (mutates g_roff += cnt)
__global__ void __launch_bounds__(256)
scatter_kernel(const float* __restrict__ pred, const float* __restrict__ target)
{
    const int i = blockIdx.x * 256 + threadIdx.x;
    if (i < NPTS) {
        const int b = i >> 12;
        const float* t = target + (size_t)i * 3;
        const float x = t[0], y = t[1], z = t[2];
        const int idx = b * RPB + cell_of(z) * G + cell_of(y);
        const int slot = atomicAdd(&g_roff[idx], 1);
        g_tpts[slot] = make_float4(x, y, z, fmaf(x, x, fmaf(y, y, z * z)));
    } else {
        const int j = i - NPTS;
        const int b = j >> 12;
        const float* p = pred + (size_t)j * 3;
        const float x = p[0], y = p[1], z = p[2];
        const int cy = cell_of(y);
        const int cz = cell_of(z);
        const int sy = (cz & 1) ? (G - 1 - cy) : cy;
        const int idx = TROWS + b * RPB + cz * G + sy;
        const int slot = atomicAdd(&g_roff[idx], 1);
        g_spred[slot] = make_float4(x, y, z, fmaf(x, x, fmaf(y, y, z * z)));
    }
}
// after scatter: start(r) = g_roff[r] - g_rcnt[r]

// ---------------------------------------------------------------- main
__global__ void __launch_bounds__(MAIN_T)
main_kernel(float* __restrict__ out)
{
    __shared__ float4 swarp[(MAIN_T / 32) * SWCAP];   // 48 KB
    __shared__ float  ssum[MAIN_T / 32];

    const int tid  = threadIdx.x;
    const int lane = tid & 31;
    const int wid  = tid >> 5;
    const int i    = blockIdx.x * MAIN_T + tid;       // sorted pred index
    const int b    = i >> 12;                         // warps never span batches

    const float4 P = g_spred[i];
    const float px = P.x, py = P.y, pz = P.z;
    const float qx = -2.0f * px, qy = -2.0f * py, qz = -2.0f * pz;
    const float p2 = P.w;
    const int cy = cell_of(py), cz = cell_of(pz);

    const int ylo = max(__reduce_min_sync(0xffffffffu, cy) - 1, 0);
    const int yhi = min(__reduce_max_sync(0xffffffffu, cy) + 1, G - 1);
    const int zlo = max(__reduce_min_sync(0xffffffffu, cz) - 1, 0);
    const int zhi = min(__reduce_max_sync(0xffffffffu, cz) + 1, G - 1);

    float4* sw = swarp + wid * SWCAP;
    int S = 0;
    bool over = false;

    // stage: one contiguous target range per z slab
    for (int z = zlo; z <= zhi; z++) {
        const int r0 = b * RPB + z * G + ylo;
        const int r1 = b * RPB + z * G + yhi;
        const int start = g_roff[r0] - g_rcnt[r0];
        const int end   = g_roff[r1];
        const int len   = end - start;
        if (S + len > SWCAP) { over = true; break; }
        for (int t = lane; t < len; t += 32)
            sw[S + t] = g_tpts[start + t];
        S += len;
    }
    __syncwarp();

    float best = 3.4e38f;           // min of s = t2 - 2 p.t
    if (!over) {
        float m0 = 3.4e38f, m1 = 3.4e38f;
        int t = 0;
        #pragma unroll 4
        for (; t + 1 < S; t += 2) {
            const float4 q0 = sw[t];
            const float4 q1 = sw[t + 1];
            m0 = fminf(m0, fmaf(qx, q0.x, fmaf(qy, q0.y, fmaf(qz, q0.z, q0.w))));
            m1 = fminf(m1, fmaf(qx, q1.x, fmaf(qy, q1.y, fmaf(qz, q1.z, q1.w))));
        }
        if (t < S) {
            const float4 q = sw[t];
            m0 = fminf(m0, fmaf(qx, q.x, fmaf(qy, q.y, fmaf(qz, q.z, q.w))));
        }
        best = fminf(m0, m1);
    }

    const float d2 = fmaxf(p2 + best, 0.0f);

    // exact stop bound: nearest non-clipped y/z face of the staged slab box
    float bnd = 3.4e38f;
    if (ylo > 0)     bnd = fminf(bnd, py - (XMIN + (float)ylo * H));
    if (yhi < G - 1) bnd = fminf(bnd, (XMIN + (float)(yhi + 1) * H) - py);
    if (zlo > 0)     bnd = fminf(bnd, pz - (XMIN + (float)zlo * H));
    if (zhi < G - 1) bnd = fminf(bnd, (XMIN + (float)(zhi + 1) * H) - pz);
    bnd = fmaxf(bnd, 0.0f);

    const bool fail = over || (S == 0) || !(d2 <= bnd * bnd);

    // warp-aggregated failure append
    const unsigned m = __ballot_sync(0xffffffffu, fail);
    if (m) {
        const int leader = __ffs(m) - 1;
        int base = 0;
        if (lane == leader) base = atomicAdd(&g_nfail, __popc(m));
        base = __shfl_sync(0xffffffffu, base, leader);
        if (fail) g_fail[base + __popc(m & ((1u << lane) - 1))] = i;
    }

    float val = fail ? 0.0f : sqrtf(d2) * INVTOT;

    #pragma unroll
    for (int o = 16; o; o >>= 1)
        val += __shfl_xor_sync(0xffffffffu, val, o);
    if (lane == 0) ssum[wid] = val;
    __syncthreads();
    if (tid < (MAIN_T / 32)) {
        float v = ssum[tid];
        #pragma unroll
        for (int o = (MAIN_T / 64); o; o >>= 1)
            v += __shfl_xor_sync(0xfu, v, o);
        if (tid == 0) atomicAdd(out, v);
    }
}

// ---------------------------------------------------------------- pass2: warp per failed pred
#define P2_T 256
#define P2_B 512

__global__ void __launch_bounds__(P2_T)
pass2_kernel(float* __restrict__ out)
{
    const int lane = threadIdx.x & 31;
    const int w    = blockIdx.x * (P2_T / 32) + (threadIdx.x >> 5);
    const int wtot = P2_B * (P2_T / 32);
    const int n    = g_nfail;

    float acc = 0.0f;

    for (int j = w; j < n; j += wtot) {
        const int i = g_fail[j];
        const int b = i >> 12;
        const float4 P = g_spred[i];
        const float qx = -2.0f * P.x, qy = -2.0f * P.y, qz = -2.0f * P.z;
        const float p2 = P.w;

        const float4* __restrict__ tp = g_tpts + (size_t)b * EMD_M;
        float m0 = 3.4e38f, m1 = 3.4e38f;
        for (int t = lane; t < EMD_M; t += 64) {
            const float4 q0 = __ldg(tp + t);
            const float4 q1 = __ldg(tp + t + 32);
            m0 = fminf(m0, fmaf(qx, q0.x, fmaf(qy, q0.y, fmaf(qz, q0.z, q0.w))));
            m1 = fminf(m1, fmaf(qx, q1.x, fmaf(qy, q1.y, fmaf(qz, q1.z, q1.w))));
        }
        float mm = fminf(m0, m1);
        #pragma unroll
        for (int o = 16; o; o >>= 1)
            mm = fminf(mm, __shfl_xor_sync(0xffffffffu, mm, o));
        if (lane == 0)
            acc += sqrtf(fmaxf(p2 + mm, 0.0f)) * INVTOT;
    }

    if (lane == 0 && acc != 0.0f)
        atomicAdd(out, acc);
}

extern "C" void kernel_launch(void* const* d_in, const int* in_sizes, int n_in,
                              void* d_out, int out_size)
{
    const float* pred   = (const float*)d_in[0];
    const float* target = (const float*)d_in[1];
    float* out = (float*)d_out;

    cudaMemsetAsync(out, 0, sizeof(float));

    void* addr = nullptr;
    cudaGetSymbolAddress(&addr, g_rcnt);
    cudaMemsetAsync(addr, 0, (size_t)(2 * TROWS) * sizeof(int));
    cudaGetSymbolAddress(&addr, g_nfail);
    cudaMemsetAsync(addr, 0, sizeof(int));

    count_kernel<<<2 * NPTS / 256, 256>>>(pred, target);
    scan_kernel<<<64, RPB>>>();
    scatter_kernel<<<2 * NPTS / 256, 256>>>(pred, target);
    main_kernel<<<NPTS / MAIN_T, MAIN_T>>>(out);
    pass2_kernel<<<P2_B, P2_T>>>(out);
}